// round 15
// baseline (speedup 1.0000x reference)
#include <cuda_runtime.h>
#include <cuda_bf16.h>
#include <cstdint>

#define Bb   4
#define Tt   1024
#define EMBD 1024
#define Hh   16
#define HEAD 64
#define BTR  (Bb * Tt)
#define NEG_BIG (-1e30f)

// Q/K/V staged as bf16: row stride 2048; cols [0,1024)=hi, [1024,2048)=lo
static __device__ __align__(16) __nv_bfloat16 g_Qb[(size_t)BTR * 2048];
static __device__ __align__(16) __nv_bfloat16 g_Kb[(size_t)BTR * 2048];
static __device__ __align__(16) __nv_bfloat16 g_Vb[(size_t)BTR * 2048];
static __device__ float g_O[(size_t)BTR * EMBD];
static __device__ float g_W[(size_t)Bb * Hh * Tt * Tt];

// ===========================================================================
// helpers
// ===========================================================================
__device__ __forceinline__ uint32_t smem_u32(const void* p) {
    uint32_t a;
    asm("{ .reg .u64 t; cvta.to.shared.u64 t, %1; cvt.u32.u64 %0, t; }" : "=r"(a) : "l"(p));
    return a;
}
__device__ __forceinline__ void ldsm4(uint32_t addr, uint32_t& r0, uint32_t& r1,
                                      uint32_t& r2, uint32_t& r3) {
    asm volatile("ldmatrix.sync.aligned.m8n8.x4.shared.b16 {%0,%1,%2,%3}, [%4];"
                 : "=r"(r0), "=r"(r1), "=r"(r2), "=r"(r3) : "r"(addr));
}
__device__ __forceinline__ void ldsm4t(uint32_t addr, uint32_t& r0, uint32_t& r1,
                                       uint32_t& r2, uint32_t& r3) {
    asm volatile("ldmatrix.sync.aligned.m8n8.x4.trans.shared.b16 {%0,%1,%2,%3}, [%4];"
                 : "=r"(r0), "=r"(r1), "=r"(r2), "=r"(r3) : "r"(addr));
}
__device__ __forceinline__ void mma_bf16(float (&d)[4], const uint32_t (&a)[4],
                                         uint32_t b0, uint32_t b1) {
    asm volatile("mma.sync.aligned.m16n8k16.row.col.f32.bf16.bf16.f32 "
                 "{%0,%1,%2,%3},{%4,%5,%6,%7},{%8,%9},{%0,%1,%2,%3};"
                 : "+f"(d[0]), "+f"(d[1]), "+f"(d[2]), "+f"(d[3])
                 : "r"(a[0]), "r"(a[1]), "r"(a[2]), "r"(a[3]), "r"(b0), "r"(b1));
}
__device__ __forceinline__ void cvt_hilo(float4 v, uint2& hi, uint2& lo) {
    __nv_bfloat162 h0 = __floats2bfloat162_rn(v.x, v.y);
    __nv_bfloat162 h1 = __floats2bfloat162_rn(v.z, v.w);
    float rx = v.x - __bfloat162float(h0.x);
    float ry = v.y - __bfloat162float(h0.y);
    float rz = v.z - __bfloat162float(h1.x);
    float rw = v.w - __bfloat162float(h1.y);
    __nv_bfloat162 l0 = __floats2bfloat162_rn(rx, ry);
    __nv_bfloat162 l1 = __floats2bfloat162_rn(rz, rw);
    hi = make_uint2(*(uint32_t*)&h0, *(uint32_t*)&h1);
    lo = make_uint2(*(uint32_t*)&l0, *(uint32_t*)&l1);
}
__device__ __forceinline__ void pack2(float x, float y, uint32_t& h, uint32_t& l) {
    __nv_bfloat162 hh = __floats2bfloat162_rn(x, y);
    float rx = x - __bfloat162float(hh.x);
    float ry = y - __bfloat162float(hh.y);
    __nv_bfloat162 ll = __floats2bfloat162_rn(rx, ry);
    h = *(uint32_t*)&hh;
    l = *(uint32_t*)&ll;
}

// ===========================================================================
// NT GEMM (C = A * B^T) — R8 mainloop. 128x128 block, BK=32, 512 threads /
// 16 warps, bf16 hi/lo 3-pass, fp32 inputs.
// WMODE 0: fp32 C.  WMODE 1: bf16 hi/lo staged C (row stride 2048).
// ===========================================================================
#define STR_K  40
#define A_HI_O 0
#define A_LO_O 10240
#define B_HI_O 20480
#define B_LO_O 30720
#define STAGE_NT 40960

template <int WMODE>
__device__ __forceinline__ void nt_body(const float* __restrict__ Ab,
                                        const float* __restrict__ Bp,
                                        float* __restrict__ Cf,
                                        __nv_bfloat16* __restrict__ Cs,
                                        char* sm, int m0, int n0)
{
    const int tid = threadIdx.x, lane = tid & 31, wid = tid >> 5;
    const int NC = EMBD / 32;

    float acc[2][4][4] = {};
    float4 la[2], lb[2];

    {
        #pragma unroll
        for (int i = 0; i < 2; i++) {
            int seg = tid + i * 512, row = seg >> 3, c4 = (seg & 7) << 2;
            la[i] = *(const float4*)&Ab[(size_t)(m0 + row) * EMBD + c4];
            lb[i] = *(const float4*)&Bp[(size_t)(n0 + row) * EMBD + c4];
        }
        #pragma unroll
        for (int i = 0; i < 2; i++) {
            int seg = tid + i * 512, row = seg >> 3, c4 = (seg & 7) << 2;
            uint2 h, l;
            cvt_hilo(la[i], h, l);
            uint32_t off = (uint32_t)(row * STR_K + c4) * 2;
            *(uint2*)(sm + A_HI_O + off) = h;
            *(uint2*)(sm + A_LO_O + off) = l;
            cvt_hilo(lb[i], h, l);
            *(uint2*)(sm + B_HI_O + off) = h;
            *(uint2*)(sm + B_LO_O + off) = l;
        }
    }
    __syncthreads();

    const int wm = wid >> 2, wn = wid & 3;
    const int arow = lane & 15, acol8 = (lane >> 4) << 3;
    const int brow = (lane & 7) + ((lane >> 4) << 3), bcol8 = ((lane >> 3) & 1) << 3;
    const uint32_t sb0 = smem_u32(sm);

    for (int c = 0; c < NC; c++) {
        if (c + 1 < NC) {
            int k0n = (c + 1) * 32;
            #pragma unroll
            for (int i = 0; i < 2; i++) {
                int seg = tid + i * 512, row = seg >> 3, c4 = (seg & 7) << 2;
                la[i] = *(const float4*)&Ab[(size_t)(m0 + row) * EMBD + k0n + c4];
                lb[i] = *(const float4*)&Bp[(size_t)(n0 + row) * EMBD + k0n + c4];
            }
        }
        const uint32_t sbase = sb0 + (c & 1) * STAGE_NT;
        #pragma unroll
        for (int ks = 0; ks < 2; ks++) {
            const int k0 = ks * 16;
            uint32_t ah[2][4], al[2][4];
            #pragma unroll
            for (int mt = 0; mt < 2; mt++) {
                int r = wm * 32 + mt * 16 + arow;
                uint32_t ad = sbase + A_HI_O + (r * STR_K + k0 + acol8) * 2;
                ldsm4(ad, ah[mt][0], ah[mt][1], ah[mt][2], ah[mt][3]);
                ldsm4(ad + (A_LO_O - A_HI_O), al[mt][0], al[mt][1], al[mt][2], al[mt][3]);
            }
            uint32_t bh[4][2], bl[4][2];
            #pragma unroll
            for (int bt = 0; bt < 2; bt++) {
                int r = wn * 32 + bt * 16 + brow;
                uint32_t bd = sbase + B_HI_O + (r * STR_K + k0 + bcol8) * 2;
                ldsm4(bd, bh[2 * bt][0], bh[2 * bt][1], bh[2 * bt + 1][0], bh[2 * bt + 1][1]);
                ldsm4(bd + (B_LO_O - B_HI_O),
                      bl[2 * bt][0], bl[2 * bt][1], bl[2 * bt + 1][0], bl[2 * bt + 1][1]);
            }
            #pragma unroll
            for (int mt = 0; mt < 2; mt++)
                #pragma unroll
                for (int nt = 0; nt < 4; nt++) {
                    mma_bf16(acc[mt][nt], ah[mt], bh[nt][0], bh[nt][1]);
                    mma_bf16(acc[mt][nt], ah[mt], bl[nt][0], bl[nt][1]);
                    mma_bf16(acc[mt][nt], al[mt], bh[nt][0], bh[nt][1]);
                }
        }
        if (c + 1 < NC) {
            char* dst = sm + ((c + 1) & 1) * STAGE_NT;
            #pragma unroll
            for (int i = 0; i < 2; i++) {
                int seg = tid + i * 512, row = seg >> 3, c4 = (seg & 7) << 2;
                uint2 h, l;
                cvt_hilo(la[i], h, l);
                uint32_t off = (uint32_t)(row * STR_K + c4) * 2;
                *(uint2*)(dst + A_HI_O + off) = h;
                *(uint2*)(dst + A_LO_O + off) = l;
                cvt_hilo(lb[i], h, l);
                *(uint2*)(dst + B_HI_O + off) = h;
                *(uint2*)(dst + B_LO_O + off) = l;
            }
        }
        __syncthreads();
    }

    const int rofs = lane >> 2, cofs = (lane & 3) * 2;
    #pragma unroll
    for (int mt = 0; mt < 2; mt++)
        #pragma unroll
        for (int nt = 0; nt < 4; nt++) {
            int m = m0 + wm * 32 + mt * 16 + rofs;
            int n = n0 + wn * 32 + nt * 8 + cofs;
            if (WMODE == 0) {
                *(float2*)&Cf[(size_t)m * EMBD + n] =
                    make_float2(acc[mt][nt][0], acc[mt][nt][1]);
                *(float2*)&Cf[(size_t)(m + 8) * EMBD + n] =
                    make_float2(acc[mt][nt][2], acc[mt][nt][3]);
            } else {
                uint32_t h0, l0, h1, l1;
                pack2(acc[mt][nt][0], acc[mt][nt][1], h0, l0);
                pack2(acc[mt][nt][2], acc[mt][nt][3], h1, l1);
                *(uint32_t*)&Cs[(size_t)m * 2048 + n]        = h0;
                *(uint32_t*)&Cs[(size_t)m * 2048 + 1024 + n] = l0;
                *(uint32_t*)&Cs[(size_t)(m + 8) * 2048 + n]        = h1;
                *(uint32_t*)&Cs[(size_t)(m + 8) * 2048 + 1024 + n] = l1;
            }
        }
}

__global__ void __launch_bounds__(512)
mma_qkv(const float* __restrict__ x, const float* __restrict__ ctx,
        const float* __restrict__ WQ, const float* __restrict__ WK,
        const float* __restrict__ WV)
{
    extern __shared__ __align__(16) char sm[];
    const int z = blockIdx.z;
    const float* Ab = (z == 0) ? x : ctx;
    const float* Bp = (z == 0) ? WQ : ((z == 1) ? WK : WV);
    __nv_bfloat16* Cs = (z == 0) ? g_Qb : ((z == 1) ? g_Kb : g_Vb);
    nt_body<1>(Ab, Bp, nullptr, Cs, sm, blockIdx.y * 128, blockIdx.x * 128);
}

__global__ void __launch_bounds__(512)
mma_out(const float* __restrict__ A, const float* __restrict__ W,
        float* __restrict__ C)
{
    extern __shared__ __align__(16) char sm[];
    nt_body<0>(A, W, C, nullptr, sm, blockIdx.y * 128, blockIdx.x * 128);
}

// ===========================================================================
// Fused attention — R8 structure (256 threads), bf16-staged Q/K/V so fills
// are pure copies. Phase 1 hi-only stats, phase 2 exact scores + weights +
// AV with exact-sum O correction.
// ===========================================================================
#define QSTR  72
#define F_LO  18432
#define FQ    0
#define FK0   36864
#define FK1   73728
#define FV0   110592
#define FV1   147456
#define FSMEM 184320

// copy a 128x64 bf16 hi/lo tile (src stride 2048; hi at +0, lo at +1024)
__device__ __forceinline__ void fillbf(const __nv_bfloat16* __restrict__ src,
                                       char* dst, int tid) {
    #pragma unroll
    for (int i = 0; i < 4; i++) {
        int seg = tid + i * 256, row = seg >> 3, j = (seg & 7) << 3;
        uint32_t off = (uint32_t)(row * QSTR + j) * 2;
        *(uint4*)(dst + off)        = *(const uint4*)&src[(size_t)row * 2048 + j];
        *(uint4*)(dst + F_LO + off) = *(const uint4*)&src[(size_t)row * 2048 + 1024 + j];
    }
}
__device__ __forceinline__ void fillbf_hi(const __nv_bfloat16* __restrict__ src,
                                          char* dst, int tid) {
    #pragma unroll
    for (int i = 0; i < 4; i++) {
        int seg = tid + i * 256, row = seg >> 3, j = (seg & 7) << 3;
        *(uint4*)(dst + (uint32_t)(row * QSTR + j) * 2) =
            *(const uint4*)&src[(size_t)row * 2048 + j];
    }
}

#define SCORE_TILE(accv, smK)                                                    \
    do {                                                                          \
        _Pragma("unroll")                                                         \
        for (int ks = 0; ks < 4; ks++) {                                          \
            uint32_t bh[16][2], bl[16][2];                                        \
            _Pragma("unroll")                                                     \
            for (int bp = 0; bp < 8; bp++) {                                      \
                uint32_t bd = (smK) + ((bp * 16 + brow) * QSTR + ks * 16 + bcol8) * 2; \
                ldsm4(bd, bh[2 * bp][0], bh[2 * bp][1], bh[2 * bp + 1][0], bh[2 * bp + 1][1]); \
                ldsm4(bd + F_LO, bl[2 * bp][0], bl[2 * bp][1], bl[2 * bp + 1][0], bl[2 * bp + 1][1]); \
            }                                                                     \
            _Pragma("unroll")                                                     \
            for (int nt = 0; nt < 16; nt++) {                                     \
                mma_bf16(accv[nt], qh[ks], bh[nt][0], bh[nt][1]);                 \
                mma_bf16(accv[nt], qh[ks], bl[nt][0], bl[nt][1]);                 \
                mma_bf16(accv[nt], ql[ks], bh[nt][0], bh[nt][1]);                 \
            }                                                                     \
        }                                                                         \
    } while (0)

#define SCORE_TILE_HI(accv, smK)                                                 \
    do {                                                                          \
        _Pragma("unroll")                                                         \
        for (int ks = 0; ks < 4; ks++) {                                          \
            uint32_t bh[16][2];                                                   \
            _Pragma("unroll")                                                     \
            for (int bp = 0; bp < 8; bp++) {                                      \
                uint32_t bd = (smK) + ((bp * 16 + brow) * QSTR + ks * 16 + bcol8) * 2; \
                ldsm4(bd, bh[2 * bp][0], bh[2 * bp][1], bh[2 * bp + 1][0], bh[2 * bp + 1][1]); \
            }                                                                     \
            _Pragma("unroll")                                                     \
            for (int nt = 0; nt < 16; nt++)                                       \
                mma_bf16(accv[nt], qh[ks], bh[nt][0], bh[nt][1]);                 \
        }                                                                         \
    } while (0)

__global__ void __launch_bounds__(256)
fused_attn(const int* __restrict__ mask,
           float* __restrict__ Wt, float* __restrict__ O, int write_w)
{
    extern __shared__ __align__(16) char sm[];
    const uint32_t sb = smem_u32(sm);
    const int tid = threadIdx.x, lane = tid & 31, w = tid >> 5;
    const int z = blockIdx.y, b = z >> 4, h = z & 15;
    const int m0 = blockIdx.x * 128;

    const __nv_bfloat16* Qb = g_Qb + ((size_t)(b * Tt + m0)) * 2048 + h * HEAD;
    const __nv_bfloat16* Kb = g_Kb + ((size_t)(b * Tt)) * 2048 + h * HEAD;
    const __nv_bfloat16* Vb = g_Vb + ((size_t)(b * Tt)) * 2048 + h * HEAD;
    const int* mb = mask + (size_t)b * Tt * Tt + (size_t)m0 * Tt;

    const int g = lane >> 2, i2 = (lane & 3) << 1;
    const int arow = lane & 15, acol8 = (lane >> 4) << 3;
    const int brow = (lane & 7) + ((lane >> 4) << 3), bcol8 = ((lane >> 3) & 1) << 3;
    const int tbrow = (lane & 7) + (((lane >> 3) & 1) << 3), tbcol8 = (lane >> 4) << 3;

    fillbf(Qb, sm + FQ, tid);
    fillbf_hi(Kb, sm + FK0, tid);
    __syncthreads();

    uint32_t qh[4][4], ql[4][4];
    #pragma unroll
    for (int ks = 0; ks < 4; ks++) {
        uint32_t ad = sb + FQ + ((w * 16 + arow) * QSTR + ks * 16 + acol8) * 2;
        ldsm4(ad, qh[ks][0], qh[ks][1], qh[ks][2], qh[ks][3]);
        ldsm4(ad + F_LO, ql[ks][0], ql[ks][1], ql[ks][2], ql[ks][3]);
    }

    const int trow = w * 16 + g;

    // ---------------- phase 1: stats (hi-only scores) ----------------
    float rm0 = -3.0e38f, rm1 = -3.0e38f, rs0 = 0.f, rs1 = 0.f;
    for (int st = 0; st < 8; st++) {
        if (st < 7) fillbf_hi(Kb + (size_t)(st + 1) * 128 * 2048,
                              sm + (((st + 1) & 1) ? FK1 : FK0), tid);
        float acc[16][4] = {};
        const uint32_t smK = sb + ((st & 1) ? FK1 : FK0);
        SCORE_TILE_HI(acc, smK);

        const int* mr0 = mb + (size_t)trow * Tt + st * 128;
        const int* mr1 = mr0 + 8 * Tt;
        #pragma unroll
        for (int nt = 0; nt < 16; nt++) {
            int2 k0 = *(const int2*)&mr0[nt * 8 + i2];
            int2 k1 = *(const int2*)&mr1[nt * 8 + i2];
            acc[nt][0] = k0.x ? NEG_BIG : acc[nt][0] * 0.125f;
            acc[nt][1] = k0.y ? NEG_BIG : acc[nt][1] * 0.125f;
            acc[nt][2] = k1.x ? NEG_BIG : acc[nt][2] * 0.125f;
            acc[nt][3] = k1.y ? NEG_BIG : acc[nt][3] * 0.125f;
        }
        float t0 = -3.0e38f, t1 = -3.0e38f;
        #pragma unroll
        for (int nt = 0; nt < 16; nt++) {
            t0 = fmaxf(t0, fmaxf(acc[nt][0], acc[nt][1]));
            t1 = fmaxf(t1, fmaxf(acc[nt][2], acc[nt][3]));
        }
        t0 = fmaxf(t0, __shfl_xor_sync(0xffffffffu, t0, 1));
        t0 = fmaxf(t0, __shfl_xor_sync(0xffffffffu, t0, 2));
        t1 = fmaxf(t1, __shfl_xor_sync(0xffffffffu, t1, 1));
        t1 = fmaxf(t1, __shfl_xor_sync(0xffffffffu, t1, 2));
        float nm0 = fmaxf(rm0, t0), nm1 = fmaxf(rm1, t1);
        float s0 = 0.f, s1 = 0.f;
        #pragma unroll
        for (int nt = 0; nt < 16; nt++) {
            s0 += __expf(acc[nt][0] - nm0) + __expf(acc[nt][1] - nm0);
            s1 += __expf(acc[nt][2] - nm1) + __expf(acc[nt][3] - nm1);
        }
        s0 += __shfl_xor_sync(0xffffffffu, s0, 1);
        s0 += __shfl_xor_sync(0xffffffffu, s0, 2);
        s1 += __shfl_xor_sync(0xffffffffu, s1, 1);
        s1 += __shfl_xor_sync(0xffffffffu, s1, 2);
        rs0 = rs0 * __expf(rm0 - nm0) + s0;  rm0 = nm0;
        rs1 = rs1 * __expf(rm1 - nm1) + s1;  rm1 = nm1;
        __syncthreads();
    }
    const float inv0 = (rm0 <= -1e29f) ? 0.f : 1.f / rs0;
    const float inv1 = (rm1 <= -1e29f) ? 0.f : 1.f / rs1;

    // ---------------- phase 2: exact scores + weights + AV ----------------
    fillbf(Kb, sm + FK0, tid);
    fillbf(Vb, sm + FV0, tid);
    __syncthreads();

    float acco[8][4] = {};
    float se0 = 0.f, se1 = 0.f;
    float* wrow0 = Wt + (size_t)z * Tt * Tt + (size_t)(m0 + trow) * Tt;
    float* wrow1 = wrow0 + 8 * Tt;

    for (int st = 0; st < 8; st++) {
        if (st < 7) {
            const int nb = (st + 1) & 1;
            fillbf(Kb + (size_t)(st + 1) * 128 * 2048, sm + (nb ? FK1 : FK0), tid);
            fillbf(Vb + (size_t)(st + 1) * 128 * 2048, sm + (nb ? FV1 : FV0), tid);
        }
        float acc[16][4] = {};
        const uint32_t smK = sb + ((st & 1) ? FK1 : FK0);
        const uint32_t smV = sb + ((st & 1) ? FV1 : FV0);
        SCORE_TILE(acc, smK);

        const int* mr0 = mb + (size_t)trow * Tt + st * 128;
        const int* mr1 = mr0 + 8 * Tt;
        float s0 = 0.f, s1 = 0.f;
        #pragma unroll
        for (int nt = 0; nt < 16; nt++) {
            int2 k0 = *(const int2*)&mr0[nt * 8 + i2];
            int2 k1 = *(const int2*)&mr1[nt * 8 + i2];
            float e0 = k0.x ? 0.f : __expf(acc[nt][0] * 0.125f - rm0);
            float e1 = k0.y ? 0.f : __expf(acc[nt][1] * 0.125f - rm0);
            float e2 = k1.x ? 0.f : __expf(acc[nt][2] * 0.125f - rm1);
            float e3 = k1.y ? 0.f : __expf(acc[nt][3] * 0.125f - rm1);
            s0 += e0 + e1;
            s1 += e2 + e3;
            acc[nt][0] = e0 * inv0;
            acc[nt][1] = e1 * inv0;
            acc[nt][2] = e2 * inv1;
            acc[nt][3] = e3 * inv1;
        }
        s0 += __shfl_xor_sync(0xffffffffu, s0, 1);
        s0 += __shfl_xor_sync(0xffffffffu, s0, 2);
        s1 += __shfl_xor_sync(0xffffffffu, s1, 1);
        s1 += __shfl_xor_sync(0xffffffffu, s1, 2);
        se0 += s0;
        se1 += s1;

        if (write_w) {
            #pragma unroll
            for (int nt = 0; nt < 16; nt++) {
                *(float2*)&wrow0[st * 128 + nt * 8 + i2] = make_float2(acc[nt][0], acc[nt][1]);
                *(float2*)&wrow1[st * 128 + nt * 8 + i2] = make_float2(acc[nt][2], acc[nt][3]);
            }
        }
        #pragma unroll
        for (int j = 0; j < 8; j++) {
            uint32_t ph[4], pl[4];
            pack2(acc[2 * j][0],     acc[2 * j][1],     ph[0], pl[0]);
            pack2(acc[2 * j][2],     acc[2 * j][3],     ph[1], pl[1]);
            pack2(acc[2 * j + 1][0], acc[2 * j + 1][1], ph[2], pl[2]);
            pack2(acc[2 * j + 1][2], acc[2 * j + 1][3], ph[3], pl[3]);
            uint32_t vh[8][2], vl[8][2];
            #pragma unroll
            for (int bt = 0; bt < 4; bt++) {
                uint32_t vd = smV + ((j * 16 + tbrow) * QSTR + bt * 16 + tbcol8) * 2;
                ldsm4t(vd, vh[2 * bt][0], vh[2 * bt][1], vh[2 * bt + 1][0], vh[2 * bt + 1][1]);
                ldsm4t(vd + F_LO, vl[2 * bt][0], vl[2 * bt][1], vl[2 * bt + 1][0], vl[2 * bt + 1][1]);
            }
            #pragma unroll
            for (int ntv = 0; ntv < 8; ntv++) {
                mma_bf16(acco[ntv], ph, vh[ntv][0], vh[ntv][1]);
                mma_bf16(acco[ntv], ph, vl[ntv][0], vl[ntv][1]);
                mma_bf16(acco[ntv], pl, vh[ntv][0], vh[ntv][1]);
            }
        }
        __syncthreads();
    }

    const float fac0 = (inv0 > 0.f && se0 > 0.f) ? 1.f / (inv0 * se0) : 0.f;
    const float fac1 = (inv1 > 0.f && se1 > 0.f) ? 1.f / (inv1 * se1) : 0.f;

    float* Ob = O + (size_t)b * Tt * EMBD + h * HEAD + (size_t)(m0 + trow) * EMBD;
    #pragma unroll
    for (int ntv = 0; ntv < 8; ntv++) {
        *(float2*)&Ob[ntv * 8 + i2] =
            make_float2(acco[ntv][0] * fac0, acco[ntv][1] * fac0);
        *(float2*)&Ob[8 * EMBD + ntv * 8 + i2] =
            make_float2(acco[ntv][2] * fac1, acco[ntv][3] * fac1);
    }
}

// ===========================================================================
extern "C" void kernel_launch(void* const* d_in, const int* in_sizes, int n_in,
                              void* d_out, int out_size)
{
    const float* x    = (const float*)d_in[0];
    const float* ctx  = (const float*)d_in[1];
    const int*   mask = (const int*)d_in[2];
    const float* WQ = (const float*)d_in[3];
    const float* WK = (const float*)d_in[4];
    const float* WV = (const float*)d_in[5];
    const float* WO = (const float*)d_in[6];
    float* out = (float*)d_out;

    float* op;
    cudaGetSymbolAddress((void**)&op, g_O);

    const size_t merged_elems = (size_t)BTR * EMBD;
    const size_t weight_elems = (size_t)Bb * Hh * Tt * Tt;
    const int write_w = ((size_t)out_size >= merged_elems + weight_elems) ? 1 : 0;
    float* wt;
    if (write_w) {
        wt = out + merged_elems;
    } else {
        cudaGetSymbolAddress((void**)&wt, g_W);
    }

    const int SMEM_NT = 2 * STAGE_NT;   // 80 KB
    cudaFuncSetAttribute(mma_qkv, cudaFuncAttributeMaxDynamicSharedMemorySize, SMEM_NT);
    cudaFuncSetAttribute(mma_out, cudaFuncAttributeMaxDynamicSharedMemorySize, SMEM_NT);
    cudaFuncSetAttribute(fused_attn, cudaFuncAttributeMaxDynamicSharedMemorySize, FSMEM);

    // Q/K/V projections (R8 mainloop), outputs staged as packed bf16 hi/lo
    dim3 gqkv(EMBD / 128, BTR / 128, 3);
    mma_qkv<<<gqkv, 512, SMEM_NT>>>(x, ctx, WQ, WK, WV);

    // fused attention (R8 two-phase, copy fills, exact-O correction)
    dim3 gf(Tt / 128, Bb * Hh);
    fused_attn<<<gf, 256, FSMEM>>>(mask, wt, op, write_w);

    // output projection (fp32 path, proven)
    dim3 gout(EMBD / 128, BTR / 128);
    mma_out<<<gout, 512, SMEM_NT>>>(op, WO, out);
}

// round 16
// speedup vs baseline: 1.0661x; 1.0661x over previous
#include <cuda_runtime.h>
#include <cuda_bf16.h>
#include <cstdint>

#define Bb   4
#define Tt   1024
#define EMBD 1024
#define Hh   16
#define HEAD 64
#define BTR  (Bb * Tt)
#define NEG_BIG (-1e30f)

static __device__ float g_Q[(size_t)BTR * EMBD];
static __device__ float g_K[(size_t)BTR * EMBD];
static __device__ float g_V[(size_t)BTR * EMBD];
static __device__ float g_O[(size_t)BTR * EMBD];
static __device__ float g_W[(size_t)Bb * Hh * Tt * Tt];

// ===========================================================================
// helpers
// ===========================================================================
__device__ __forceinline__ uint32_t smem_u32(const void* p) {
    uint32_t a;
    asm("{ .reg .u64 t; cvta.to.shared.u64 t, %1; cvt.u32.u64 %0, t; }" : "=r"(a) : "l"(p));
    return a;
}
__device__ __forceinline__ void ldsm4(uint32_t addr, uint32_t& r0, uint32_t& r1,
                                      uint32_t& r2, uint32_t& r3) {
    asm volatile("ldmatrix.sync.aligned.m8n8.x4.shared.b16 {%0,%1,%2,%3}, [%4];"
                 : "=r"(r0), "=r"(r1), "=r"(r2), "=r"(r3) : "r"(addr));
}
__device__ __forceinline__ void ldsm4t(uint32_t addr, uint32_t& r0, uint32_t& r1,
                                       uint32_t& r2, uint32_t& r3) {
    asm volatile("ldmatrix.sync.aligned.m8n8.x4.trans.shared.b16 {%0,%1,%2,%3}, [%4];"
                 : "=r"(r0), "=r"(r1), "=r"(r2), "=r"(r3) : "r"(addr));
}
__device__ __forceinline__ void mma_bf16(float (&d)[4], const uint32_t (&a)[4],
                                         uint32_t b0, uint32_t b1) {
    asm volatile("mma.sync.aligned.m16n8k16.row.col.f32.bf16.bf16.f32 "
                 "{%0,%1,%2,%3},{%4,%5,%6,%7},{%8,%9},{%0,%1,%2,%3};"
                 : "+f"(d[0]), "+f"(d[1]), "+f"(d[2]), "+f"(d[3])
                 : "r"(a[0]), "r"(a[1]), "r"(a[2]), "r"(a[3]), "r"(b0), "r"(b1));
}
__device__ __forceinline__ void cvt_hilo(float4 v, uint2& hi, uint2& lo) {
    __nv_bfloat162 h0 = __floats2bfloat162_rn(v.x, v.y);
    __nv_bfloat162 h1 = __floats2bfloat162_rn(v.z, v.w);
    float rx = v.x - __bfloat162float(h0.x);
    float ry = v.y - __bfloat162float(h0.y);
    float rz = v.z - __bfloat162float(h1.x);
    float rw = v.w - __bfloat162float(h1.y);
    __nv_bfloat162 l0 = __floats2bfloat162_rn(rx, ry);
    __nv_bfloat162 l1 = __floats2bfloat162_rn(rz, rw);
    hi = make_uint2(*(uint32_t*)&h0, *(uint32_t*)&h1);
    lo = make_uint2(*(uint32_t*)&l0, *(uint32_t*)&l1);
}
__device__ __forceinline__ void pack2(float x, float y, uint32_t& h, uint32_t& l) {
    __nv_bfloat162 hh = __floats2bfloat162_rn(x, y);
    float rx = x - __bfloat162float(hh.x);
    float ry = y - __bfloat162float(hh.y);
    __nv_bfloat162 ll = __floats2bfloat162_rn(rx, ry);
    h = *(uint32_t*)&hh;
    l = *(uint32_t*)&ll;
}

// ===========================================================================
// NT GEMM (C = A * B^T) — exact R8 version. 128x128 block, BK=32,
// 512 threads / 16 warps, bf16 hi/lo 3-pass, fp32 in/out.
// ===========================================================================
#define STR_K  40
#define A_HI_O 0
#define A_LO_O 10240
#define B_HI_O 20480
#define B_LO_O 30720
#define STAGE_NT 40960

__device__ __forceinline__ void nt_body(const float* __restrict__ Ab,
                                        const float* __restrict__ Bp,
                                        float* __restrict__ Cb, char* sm,
                                        int m0, int n0)
{
    const int tid = threadIdx.x, lane = tid & 31, wid = tid >> 5;
    const int NC = EMBD / 32;

    float acc[2][4][4] = {};
    float4 la[2], lb[2];

    {
        #pragma unroll
        for (int i = 0; i < 2; i++) {
            int seg = tid + i * 512, row = seg >> 3, c4 = (seg & 7) << 2;
            la[i] = *(const float4*)&Ab[(size_t)(m0 + row) * EMBD + c4];
            lb[i] = *(const float4*)&Bp[(size_t)(n0 + row) * EMBD + c4];
        }
        #pragma unroll
        for (int i = 0; i < 2; i++) {
            int seg = tid + i * 512, row = seg >> 3, c4 = (seg & 7) << 2;
            uint2 h, l;
            cvt_hilo(la[i], h, l);
            uint32_t off = (uint32_t)(row * STR_K + c4) * 2;
            *(uint2*)(sm + A_HI_O + off) = h;
            *(uint2*)(sm + A_LO_O + off) = l;
            cvt_hilo(lb[i], h, l);
            *(uint2*)(sm + B_HI_O + off) = h;
            *(uint2*)(sm + B_LO_O + off) = l;
        }
    }
    __syncthreads();

    const int wm = wid >> 2, wn = wid & 3;
    const int arow = lane & 15, acol8 = (lane >> 4) << 3;
    const int brow = (lane & 7) + ((lane >> 4) << 3), bcol8 = ((lane >> 3) & 1) << 3;
    const uint32_t sb0 = smem_u32(sm);

    for (int c = 0; c < NC; c++) {
        if (c + 1 < NC) {
            int k0n = (c + 1) * 32;
            #pragma unroll
            for (int i = 0; i < 2; i++) {
                int seg = tid + i * 512, row = seg >> 3, c4 = (seg & 7) << 2;
                la[i] = *(const float4*)&Ab[(size_t)(m0 + row) * EMBD + k0n + c4];
                lb[i] = *(const float4*)&Bp[(size_t)(n0 + row) * EMBD + k0n + c4];
            }
        }
        const uint32_t sbase = sb0 + (c & 1) * STAGE_NT;
        #pragma unroll
        for (int ks = 0; ks < 2; ks++) {
            const int k0 = ks * 16;
            uint32_t ah[2][4], al[2][4];
            #pragma unroll
            for (int mt = 0; mt < 2; mt++) {
                int r = wm * 32 + mt * 16 + arow;
                uint32_t ad = sbase + A_HI_O + (r * STR_K + k0 + acol8) * 2;
                ldsm4(ad, ah[mt][0], ah[mt][1], ah[mt][2], ah[mt][3]);
                ldsm4(ad + (A_LO_O - A_HI_O), al[mt][0], al[mt][1], al[mt][2], al[mt][3]);
            }
            uint32_t bh[4][2], bl[4][2];
            #pragma unroll
            for (int bt = 0; bt < 2; bt++) {
                int r = wn * 32 + bt * 16 + brow;
                uint32_t bd = sbase + B_HI_O + (r * STR_K + k0 + bcol8) * 2;
                ldsm4(bd, bh[2 * bt][0], bh[2 * bt][1], bh[2 * bt + 1][0], bh[2 * bt + 1][1]);
                ldsm4(bd + (B_LO_O - B_HI_O),
                      bl[2 * bt][0], bl[2 * bt][1], bl[2 * bt + 1][0], bl[2 * bt + 1][1]);
            }
            #pragma unroll
            for (int mt = 0; mt < 2; mt++)
                #pragma unroll
                for (int nt = 0; nt < 4; nt++) {
                    mma_bf16(acc[mt][nt], ah[mt], bh[nt][0], bh[nt][1]);
                    mma_bf16(acc[mt][nt], ah[mt], bl[nt][0], bl[nt][1]);
                    mma_bf16(acc[mt][nt], al[mt], bh[nt][0], bh[nt][1]);
                }
        }
        if (c + 1 < NC) {
            char* dst = sm + ((c + 1) & 1) * STAGE_NT;
            #pragma unroll
            for (int i = 0; i < 2; i++) {
                int seg = tid + i * 512, row = seg >> 3, c4 = (seg & 7) << 2;
                uint2 h, l;
                cvt_hilo(la[i], h, l);
                uint32_t off = (uint32_t)(row * STR_K + c4) * 2;
                *(uint2*)(dst + A_HI_O + off) = h;
                *(uint2*)(dst + A_LO_O + off) = l;
                cvt_hilo(lb[i], h, l);
                *(uint2*)(dst + B_HI_O + off) = h;
                *(uint2*)(dst + B_LO_O + off) = l;
            }
        }
        __syncthreads();
    }

    const int rofs = lane >> 2, cofs = (lane & 3) * 2;
    #pragma unroll
    for (int mt = 0; mt < 2; mt++)
        #pragma unroll
        for (int nt = 0; nt < 4; nt++) {
            int m = m0 + wm * 32 + mt * 16 + rofs;
            int n = n0 + wn * 32 + nt * 8 + cofs;
            *(float2*)&Cb[(size_t)m * EMBD + n] =
                make_float2(acc[mt][nt][0], acc[mt][nt][1]);
            *(float2*)&Cb[(size_t)(m + 8) * EMBD + n] =
                make_float2(acc[mt][nt][2], acc[mt][nt][3]);
        }
}

__global__ void __launch_bounds__(512)
mma_qkv(const float* __restrict__ x, const float* __restrict__ ctx,
        const float* __restrict__ WQ, const float* __restrict__ WK,
        const float* __restrict__ WV,
        float* __restrict__ qp, float* __restrict__ kp, float* __restrict__ vp)
{
    extern __shared__ __align__(16) char sm[];
    const int z = blockIdx.z;
    const float* Ab = (z == 0) ? x : ctx;
    const float* Bp = (z == 0) ? WQ : ((z == 1) ? WK : WV);
    float* Cb = (z == 0) ? qp : ((z == 1) ? kp : vp);
    nt_body(Ab, Bp, Cb, sm, blockIdx.y * 128, blockIdx.x * 128);
}

__global__ void __launch_bounds__(512)
mma_out(const float* __restrict__ A, const float* __restrict__ W,
        float* __restrict__ C)
{
    extern __shared__ __align__(16) char sm[];
    nt_body(A, W, C, sm, blockIdx.y * 128, blockIdx.x * 128);
}

// ===========================================================================
// Fused attention (R8 structure, 256 threads): phase 1 hi-only stats,
// phase 2 exact scores + weights + AV with exact-sum O correction.
// Cross-phase prefetch: phase-1 st=5/6 fill phase-2's first K/V tiles into
// the (dead) FV0/FV1 buffers; phase 2 alternates K in {FV1, FK0} and V in
// {FV0, FK1} — no inter-phase fill bubble.
// ===========================================================================
#define QSTR  72
#define F_LO  18432
#define FQ    0
#define FK0   36864
#define FK1   73728
#define FV0   110592
#define FV1   147456
#define FSMEM 184320

__device__ __forceinline__ void fill64(const float* __restrict__ src, char* dst, int tid) {
    #pragma unroll
    for (int i = 0; i < 8; i++) {
        int seg = tid + i * 256, row = seg >> 4, c4 = (seg & 15) << 2;
        float4 v = *(const float4*)&src[(size_t)row * EMBD + c4];
        uint2 h, l;
        cvt_hilo(v, h, l);
        uint32_t off = (uint32_t)(row * QSTR + c4) * 2;
        *(uint2*)(dst + off) = h;
        *(uint2*)(dst + F_LO + off) = l;
    }
}
__device__ __forceinline__ void fill64_hi(const float* __restrict__ src, char* dst, int tid) {
    #pragma unroll
    for (int i = 0; i < 8; i++) {
        int seg = tid + i * 256, row = seg >> 4, c4 = (seg & 15) << 2;
        float4 v = *(const float4*)&src[(size_t)row * EMBD + c4];
        __nv_bfloat162 h0 = __floats2bfloat162_rn(v.x, v.y);
        __nv_bfloat162 h1 = __floats2bfloat162_rn(v.z, v.w);
        uint32_t off = (uint32_t)(row * QSTR + c4) * 2;
        *(uint2*)(dst + off) = make_uint2(*(uint32_t*)&h0, *(uint32_t*)&h1);
    }
}

#define SCORE_TILE(accv, smK)                                                    \
    do {                                                                          \
        _Pragma("unroll")                                                         \
        for (int ks = 0; ks < 4; ks++) {                                          \
            uint32_t bh[16][2], bl[16][2];                                        \
            _Pragma("unroll")                                                     \
            for (int bp = 0; bp < 8; bp++) {                                      \
                uint32_t bd = (smK) + ((bp * 16 + brow) * QSTR + ks * 16 + bcol8) * 2; \
                ldsm4(bd, bh[2 * bp][0], bh[2 * bp][1], bh[2 * bp + 1][0], bh[2 * bp + 1][1]); \
                ldsm4(bd + F_LO, bl[2 * bp][0], bl[2 * bp][1], bl[2 * bp + 1][0], bl[2 * bp + 1][1]); \
            }                                                                     \
            _Pragma("unroll")                                                     \
            for (int nt = 0; nt < 16; nt++) {                                     \
                mma_bf16(accv[nt], qh[ks], bh[nt][0], bh[nt][1]);                 \
                mma_bf16(accv[nt], qh[ks], bl[nt][0], bl[nt][1]);                 \
                mma_bf16(accv[nt], ql[ks], bh[nt][0], bh[nt][1]);                 \
            }                                                                     \
        }                                                                         \
    } while (0)

#define SCORE_TILE_HI(accv, smK)                                                 \
    do {                                                                          \
        _Pragma("unroll")                                                         \
        for (int ks = 0; ks < 4; ks++) {                                          \
            uint32_t bh[16][2];                                                   \
            _Pragma("unroll")                                                     \
            for (int bp = 0; bp < 8; bp++) {                                      \
                uint32_t bd = (smK) + ((bp * 16 + brow) * QSTR + ks * 16 + bcol8) * 2; \
                ldsm4(bd, bh[2 * bp][0], bh[2 * bp][1], bh[2 * bp + 1][0], bh[2 * bp + 1][1]); \
            }                                                                     \
            _Pragma("unroll")                                                     \
            for (int nt = 0; nt < 16; nt++)                                       \
                mma_bf16(accv[nt], qh[ks], bh[nt][0], bh[nt][1]);                 \
        }                                                                         \
    } while (0)

__global__ void __launch_bounds__(256)
fused_attn(const float* __restrict__ Q, const float* __restrict__ K,
           const float* __restrict__ V, const int* __restrict__ mask,
           float* __restrict__ Wt, float* __restrict__ O, int write_w)
{
    extern __shared__ __align__(16) char sm[];
    const uint32_t sb = smem_u32(sm);
    const int tid = threadIdx.x, lane = tid & 31, w = tid >> 5;
    const int z = blockIdx.y, b = z >> 4, h = z & 15;
    const int m0 = blockIdx.x * 128;

    const float* Qb = Q + (size_t)b * Tt * EMBD + h * HEAD;
    const float* Kb = K + (size_t)b * Tt * EMBD + h * HEAD;
    const float* Vb = V + (size_t)b * Tt * EMBD + h * HEAD;
    const int* mb = mask + (size_t)b * Tt * Tt + (size_t)m0 * Tt;

    const int g = lane >> 2, i2 = (lane & 3) << 1;
    const int arow = lane & 15, acol8 = (lane >> 4) << 3;
    const int brow = (lane & 7) + ((lane >> 4) << 3), bcol8 = ((lane >> 3) & 1) << 3;
    const int tbrow = (lane & 7) + (((lane >> 3) & 1) << 3), tbcol8 = (lane >> 4) << 3;

    fill64(Qb + (size_t)m0 * EMBD, sm + FQ, tid);
    fill64_hi(Kb, sm + FK0, tid);
    __syncthreads();

    // hoist Q-hi fragments only (ql loaded after phase 1)
    uint32_t qh[4][4], ql[4][4];
    #pragma unroll
    for (int ks = 0; ks < 4; ks++) {
        uint32_t ad = sb + FQ + ((w * 16 + arow) * QSTR + ks * 16 + acol8) * 2;
        ldsm4(ad, qh[ks][0], qh[ks][1], qh[ks][2], qh[ks][3]);
    }

    const int trow = w * 16 + g;

    // ---------------- phase 1: stats (hi-only scores) ----------------
    float rm0 = -3.0e38f, rm1 = -3.0e38f, rs0 = 0.f, rs1 = 0.f;
    for (int st = 0; st < 8; st++) {
        if (st < 7) fill64_hi(Kb + (size_t)(st + 1) * 128 * EMBD,
                              sm + (((st + 1) & 1) ? FK1 : FK0), tid);
        // cross-phase prefetch into dead V buffers
        if (st == 5) fill64(Vb, sm + FV0, tid);        // phase-2 V0 (full)
        if (st == 6) fill64(Kb, sm + FV1, tid);        // phase-2 K0 (full)

        float acc[16][4] = {};
        const uint32_t smK = sb + ((st & 1) ? FK1 : FK0);
        SCORE_TILE_HI(acc, smK);

        const int* mr0 = mb + (size_t)trow * Tt + st * 128;
        const int* mr1 = mr0 + 8 * Tt;
        #pragma unroll
        for (int nt = 0; nt < 16; nt++) {
            int2 k0 = *(const int2*)&mr0[nt * 8 + i2];
            int2 k1 = *(const int2*)&mr1[nt * 8 + i2];
            acc[nt][0] = k0.x ? NEG_BIG : acc[nt][0] * 0.125f;
            acc[nt][1] = k0.y ? NEG_BIG : acc[nt][1] * 0.125f;
            acc[nt][2] = k1.x ? NEG_BIG : acc[nt][2] * 0.125f;
            acc[nt][3] = k1.y ? NEG_BIG : acc[nt][3] * 0.125f;
        }
        float t0 = -3.0e38f, t1 = -3.0e38f;
        #pragma unroll
        for (int nt = 0; nt < 16; nt++) {
            t0 = fmaxf(t0, fmaxf(acc[nt][0], acc[nt][1]));
            t1 = fmaxf(t1, fmaxf(acc[nt][2], acc[nt][3]));
        }
        t0 = fmaxf(t0, __shfl_xor_sync(0xffffffffu, t0, 1));
        t0 = fmaxf(t0, __shfl_xor_sync(0xffffffffu, t0, 2));
        t1 = fmaxf(t1, __shfl_xor_sync(0xffffffffu, t1, 1));
        t1 = fmaxf(t1, __shfl_xor_sync(0xffffffffu, t1, 2));
        float nm0 = fmaxf(rm0, t0), nm1 = fmaxf(rm1, t1);
        float s0 = 0.f, s1 = 0.f;
        #pragma unroll
        for (int nt = 0; nt < 16; nt++) {
            s0 += __expf(acc[nt][0] - nm0) + __expf(acc[nt][1] - nm0);
            s1 += __expf(acc[nt][2] - nm1) + __expf(acc[nt][3] - nm1);
        }
        s0 += __shfl_xor_sync(0xffffffffu, s0, 1);
        s0 += __shfl_xor_sync(0xffffffffu, s0, 2);
        s1 += __shfl_xor_sync(0xffffffffu, s1, 1);
        s1 += __shfl_xor_sync(0xffffffffu, s1, 2);
        rs0 = rs0 * __expf(rm0 - nm0) + s0;  rm0 = nm0;
        rs1 = rs1 * __expf(rm1 - nm1) + s1;  rm1 = nm1;
        __syncthreads();
    }
    const float inv0 = (rm0 <= -1e29f) ? 0.f : 1.f / rs0;
    const float inv1 = (rm1 <= -1e29f) ? 0.f : 1.f / rs1;

    // ql hoist (Q smem still intact)
    #pragma unroll
    for (int ks = 0; ks < 4; ks++) {
        uint32_t ad = sb + FQ + ((w * 16 + arow) * QSTR + ks * 16 + acol8) * 2;
        ldsm4(ad + F_LO, ql[ks][0], ql[ks][1], ql[ks][2], ql[ks][3]);
    }

    // ---------------- phase 2: exact scores + weights + AV ----------------
    // buffers prefetched during phase 1: K0-full in FV1, V0-full in FV0.
    // K tiles: even st -> FV1, odd -> FK0.  V tiles: even -> FV0, odd -> FK1.
    float acco[8][4] = {};
    float se0 = 0.f, se1 = 0.f;
    float* wrow0 = Wt + (size_t)z * Tt * Tt + (size_t)(m0 + trow) * Tt;
    float* wrow1 = wrow0 + 8 * Tt;

    for (int st = 0; st < 8; st++) {
        if (st < 7) {
            const int no = (st + 1) & 1;   // 1 -> odd
            fill64(Kb + (size_t)(st + 1) * 128 * EMBD, sm + (no ? FK0 : FV1), tid);
            fill64(Vb + (size_t)(st + 1) * 128 * EMBD, sm + (no ? FK1 : FV0), tid);
        }
        float acc[16][4] = {};
        const uint32_t smK = sb + ((st & 1) ? FK0 : FV1);
        const uint32_t smV = sb + ((st & 1) ? FK1 : FV0);
        SCORE_TILE(acc, smK);

        const int* mr0 = mb + (size_t)trow * Tt + st * 128;
        const int* mr1 = mr0 + 8 * Tt;
        float s0 = 0.f, s1 = 0.f;
        #pragma unroll
        for (int nt = 0; nt < 16; nt++) {
            int2 k0 = *(const int2*)&mr0[nt * 8 + i2];
            int2 k1 = *(const int2*)&mr1[nt * 8 + i2];
            float e0 = k0.x ? 0.f : __expf(acc[nt][0] * 0.125f - rm0);
            float e1 = k0.y ? 0.f : __expf(acc[nt][1] * 0.125f - rm0);
            float e2 = k1.x ? 0.f : __expf(acc[nt][2] * 0.125f - rm1);
            float e3 = k1.y ? 0.f : __expf(acc[nt][3] * 0.125f - rm1);
            s0 += e0 + e1;
            s1 += e2 + e3;
            acc[nt][0] = e0 * inv0;
            acc[nt][1] = e1 * inv0;
            acc[nt][2] = e2 * inv1;
            acc[nt][3] = e3 * inv1;
        }
        s0 += __shfl_xor_sync(0xffffffffu, s0, 1);
        s0 += __shfl_xor_sync(0xffffffffu, s0, 2);
        s1 += __shfl_xor_sync(0xffffffffu, s1, 1);
        s1 += __shfl_xor_sync(0xffffffffu, s1, 2);
        se0 += s0;
        se1 += s1;

        if (write_w) {
            #pragma unroll
            for (int nt = 0; nt < 16; nt++) {
                *(float2*)&wrow0[st * 128 + nt * 8 + i2] = make_float2(acc[nt][0], acc[nt][1]);
                *(float2*)&wrow1[st * 128 + nt * 8 + i2] = make_float2(acc[nt][2], acc[nt][3]);
            }
        }
        #pragma unroll
        for (int j = 0; j < 8; j++) {
            uint32_t ph[4], pl[4];
            pack2(acc[2 * j][0],     acc[2 * j][1],     ph[0], pl[0]);
            pack2(acc[2 * j][2],     acc[2 * j][3],     ph[1], pl[1]);
            pack2(acc[2 * j + 1][0], acc[2 * j + 1][1], ph[2], pl[2]);
            pack2(acc[2 * j + 1][2], acc[2 * j + 1][3], ph[3], pl[3]);
            uint32_t vh[8][2], vl[8][2];
            #pragma unroll
            for (int bt = 0; bt < 4; bt++) {
                uint32_t vd = smV + ((j * 16 + tbrow) * QSTR + bt * 16 + tbcol8) * 2;
                ldsm4t(vd, vh[2 * bt][0], vh[2 * bt][1], vh[2 * bt + 1][0], vh[2 * bt + 1][1]);
                ldsm4t(vd + F_LO, vl[2 * bt][0], vl[2 * bt][1], vl[2 * bt + 1][0], vl[2 * bt + 1][1]);
            }
            #pragma unroll
            for (int ntv = 0; ntv < 8; ntv++) {
                mma_bf16(acco[ntv], ph, vh[ntv][0], vh[ntv][1]);
                mma_bf16(acco[ntv], ph, vl[ntv][0], vl[ntv][1]);
                mma_bf16(acco[ntv], pl, vh[ntv][0], vh[ntv][1]);
            }
        }
        __syncthreads();
    }

    // exact-O correction: acco accumulated with e*inv; exact O = acco/(inv*se)
    const float fac0 = (inv0 > 0.f && se0 > 0.f) ? 1.f / (inv0 * se0) : 0.f;
    const float fac1 = (inv1 > 0.f && se1 > 0.f) ? 1.f / (inv1 * se1) : 0.f;

    float* Ob = O + (size_t)b * Tt * EMBD + h * HEAD + (size_t)(m0 + trow) * EMBD;
    #pragma unroll
    for (int ntv = 0; ntv < 8; ntv++) {
        *(float2*)&Ob[ntv * 8 + i2] =
            make_float2(acco[ntv][0] * fac0, acco[ntv][1] * fac0);
        *(float2*)&Ob[8 * EMBD + ntv * 8 + i2] =
            make_float2(acco[ntv][2] * fac1, acco[ntv][3] * fac1);
    }
}

// ===========================================================================
extern "C" void kernel_launch(void* const* d_in, const int* in_sizes, int n_in,
                              void* d_out, int out_size)
{
    const float* x    = (const float*)d_in[0];
    const float* ctx  = (const float*)d_in[1];
    const int*   mask = (const int*)d_in[2];
    const float* WQ = (const float*)d_in[3];
    const float* WK = (const float*)d_in[4];
    const float* WV = (const float*)d_in[5];
    const float* WO = (const float*)d_in[6];
    float* out = (float*)d_out;

    float *qp, *kp, *vp, *op;
    cudaGetSymbolAddress((void**)&qp, g_Q);
    cudaGetSymbolAddress((void**)&kp, g_K);
    cudaGetSymbolAddress((void**)&vp, g_V);
    cudaGetSymbolAddress((void**)&op, g_O);

    const size_t merged_elems = (size_t)BTR * EMBD;
    const size_t weight_elems = (size_t)Bb * Hh * Tt * Tt;
    const int write_w = ((size_t)out_size >= merged_elems + weight_elems) ? 1 : 0;
    float* wt;
    if (write_w) {
        wt = out + merged_elems;
    } else {
        cudaGetSymbolAddress((void**)&wt, g_W);
    }

    const int SMEM_NT = 2 * STAGE_NT;   // 80 KB
    cudaFuncSetAttribute(mma_qkv, cudaFuncAttributeMaxDynamicSharedMemorySize, SMEM_NT);
    cudaFuncSetAttribute(mma_out, cudaFuncAttributeMaxDynamicSharedMemorySize, SMEM_NT);
    cudaFuncSetAttribute(fused_attn, cudaFuncAttributeMaxDynamicSharedMemorySize, FSMEM);

    // Q/K/V projections (R8 proven, fp32 in/out)
    dim3 gqkv(EMBD / 128, BTR / 128, 3);
    mma_qkv<<<gqkv, 512, SMEM_NT>>>(x, ctx, WQ, WK, WV, qp, kp, vp);

    // fused attention (R8 two-phase + cross-phase prefetch + exact-O corr)
    dim3 gf(Tt / 128, Bb * Hh);
    fused_attn<<<gf, 256, FSMEM>>>(qp, kp, vp, mask, wt, op, write_w);

    // output projection (R8 proven)
    dim3 gout(EMBD / 128, BTR / 128);
    mma_out<<<gout, 512, SMEM_NT>>>(op, WO, out);
}